// round 10
// baseline (speedup 1.0000x reference)
#include <cuda_runtime.h>
#include <cstdint>

#define RES      64
#define N_PHAL   20
#define MAX_B    256

constexpr int FLT_PER_CHUNK  = RES * RES * 5;                  // 20480 floats = 80 KB
constexpr int NSTAGE         = 4;                              // ring depth = 1 unit
constexpr int SUB_FLT        = 2560;                           // 10 KB subtile
constexpr int SUB_POS        = SUB_FLT / 5;                    // 512 positions
constexpr unsigned SUB_BYTES = SUB_FLT * 4;                    // 10240
constexpr int THREADS        = 256;
constexpr int GRID           = 740;                            // 148 SMs x 5 CTAs

// Scratch: per chunk 8 floats: A,Bm,C,D,E,F,den,(pad). Accumulated by atomicAdd,
// exactly 2 partials per chunk (commutative -> deterministic). Re-zeroed each run.
__device__ float        g_scratch[MAX_B * N_PHAL * 8];   // zero-initialized
__device__ unsigned int g_count = 0;
__device__ unsigned int g_next  = 0;    // work-stealing unit counter

__device__ __forceinline__ float warp_red(float v) {
    #pragma unroll
    for (int o = 16; o > 0; o >>= 1)
        v += __shfl_down_sync(0xffffffffu, v, o);
    return v;
}

__device__ __forceinline__ void mbar_init(unsigned int mbar, unsigned int count) {
    asm volatile("mbarrier.init.shared.b64 [%0], %1;" :: "r"(mbar), "r"(count) : "memory");
}
__device__ __forceinline__ void mbar_expect_tx(unsigned int mbar, unsigned int bytes) {
    asm volatile("mbarrier.arrive.expect_tx.shared.b64 _, [%0], %1;"
                 :: "r"(mbar), "r"(bytes) : "memory");
}
__device__ __forceinline__ void mbar_wait(unsigned int mbar, unsigned int parity) {
    unsigned int done;
    asm volatile(
        "{\n\t.reg .pred p;\n\t"
        "mbarrier.try_wait.parity.acquire.cta.shared::cta.b64 p, [%1], %2;\n\t"
        "selp.b32 %0, 1, 0, p;\n\t}"
        : "=r"(done) : "r"(mbar), "r"(parity) : "memory");
    if (!done) {
        asm volatile(
            "{\n\t.reg .pred P1;\n\t"
            "WAIT_LOOP_%=:\n\t"
            "mbarrier.try_wait.parity.acquire.cta.shared::cta.b64 P1, [%0], %1, 0x989680;\n\t"
            "@P1 bra.uni WAIT_DONE_%=;\n\t"
            "bra.uni WAIT_LOOP_%=;\n\t"
            "WAIT_DONE_%=:\n\t}"
            :: "r"(mbar), "r"(parity) : "memory");
    }
}
__device__ __forceinline__ void bulk_g2s(unsigned int dst, const void* src,
                                         unsigned int bytes, unsigned int mbar) {
    asm volatile(
        "cp.async.bulk.shared::cta.global.mbarrier::complete_tx::bytes [%0], [%1], %2, [%3];"
        :: "r"(dst), "l"(src), "r"(bytes), "r"(mbar) : "memory");
}

__global__ __launch_bounds__(THREADS, 5) void fused_kernel(
    const float* __restrict__ x, float* __restrict__ scratch,
    float* __restrict__ out, int total_chunks)
{
    __shared__ alignas(16) float buf[NSTAGE][SUB_FLT];   // 4 x 10 KB ring
    __shared__ alignas(8)  unsigned long long mbar_st[NSTAGE];
    __shared__ float red[8][7];
    __shared__ int   units_sm[2];         // double-buffered stolen unit ids
    __shared__ int   s_last;

    const int t           = threadIdx.x;
    const int grid        = gridDim.x;
    const int total_units = total_chunks * 2;   // unit = half chunk = 4 subtiles

    unsigned int mb0 = (unsigned int)__cvta_generic_to_shared(&mbar_st[0]);
    unsigned int sb0 = (unsigned int)__cvta_generic_to_shared(&buf[0][0]);

    if (t == 0) {
        #pragma unroll
        for (int i = 0; i < NSTAGE; ++i) mbar_init(mb0 + i * 8, 1);
        unsigned int id = atomicAdd(&g_next, 1u);           // first unit
        units_sm[0] = (id < (unsigned)total_units) ? (int)id : -1;
        units_sm[1] = -1;
    }
    __syncthreads();

    // ---- prologue: issue all 4 stages of unit 0 ----
    if (t == 0 && units_sm[0] >= 0) {
        int u = units_sm[0];
        const float* ub = x + (size_t)(u >> 1) * FLT_PER_CHUNK
                            + (u & 1) * (4 * SUB_FLT);
        #pragma unroll
        for (int p = 0; p < NSTAGE; ++p) {
            mbar_expect_tx(mb0 + p * 8, SUB_BYTES);
            bulk_g2s(sb0 + p * (SUB_FLT * 4), ub + p * SUB_FLT,
                     SUB_BYTES, mb0 + p * 8);
        }
    }

    float A = 0.f, Bm = 0.f, C = 0.f, D = 0.f, E = 0.f, F = 0.f, den = 0.f;

    for (int st = 0; ; ++st) {
        const int slot = (st >> 2) & 1;
        const int u    = units_sm[slot];      // stable: >=1 __syncthreads since write
        if (u < 0) break;

        const int b = st & 3;
        mbar_wait(mb0 + b * 8, (st >> 2) & 1);

        // this thread's 2 positions: 10 floats at 40B offset; 5 x LDS.64
        const float2* s2 = (const float2*)(buf[b] + t * 10);
        float2 w0 = s2[0];   // f0A f1A
        float2 w1 = s2[1];   // mA  d0A
        float2 w2 = s2[2];   // d1A f0B
        float2 w3 = s2[3];   // f1B mB
        float2 w4 = s2[4];   // d0B d1B

        int sub_in_chunk = (u & 1) * 4 + (st & 3);
        int pos0 = sub_in_chunk * SUB_POS + t * 2;
        float fi = (float)(pos0 >> 6);        // row (2 | 64 -> same for both)
        float fj = (float)(pos0 & 63);

        // position A
        { float m = w1.x, am = fabsf(m), sc = m * am;
          float t0 = sc * w0.x, t1 = sc * w0.y;
          A  = fmaf(t1, w1.y, A);  Bm = fmaf(t0, w1.y, Bm);
          C  = fmaf(t1, w2.x, C);  D  = fmaf(t0, w2.x, D);
          E  = fmaf(am, fi, E);    F  = fmaf(am, fj, F);
          den += am; }
        // position B
        { float m = w3.y, am = fabsf(m), sc = m * am;
          float t0 = sc * w2.y, t1 = sc * w3.x;
          A  = fmaf(t1, w4.x, A);  Bm = fmaf(t0, w4.x, Bm);
          C  = fmaf(t1, w4.y, C);  D  = fmaf(t0, w4.y, D);
          E  = fmaf(am, fi, E);    F  = fmaf(am, fj + 1.f, F);
          den += am; }

        __syncthreads();                      // all threads done reading buf[b]

        // ---- t0: steal next unit at horizon + issue stage st+4 ----
        if (t == 0) {
            int st2 = st + NSTAGE;
            int sl2 = (st2 >> 2) & 1;         // opposite slot
            if ((st2 & 3) == 0) {             // entering a new unit: steal
                unsigned int id = atomicAdd(&g_next, 1u);
                units_sm[sl2] = (id < (unsigned)total_units) ? (int)id : -1;
            }
            int u2 = units_sm[sl2];
            if (u2 >= 0) {
                int b2 = st2 & 3;
                const float* src = x + (size_t)(u2 >> 1) * FLT_PER_CHUNK
                                     + ((u2 & 1) * 4 + (st2 & 3)) * SUB_FLT;
                mbar_expect_tx(mb0 + b2 * 8, SUB_BYTES);
                bulk_g2s(sb0 + b2 * (SUB_FLT * 4), src, SUB_BYTES, mb0 + b2 * 8);
            }
        }

        // ---- per-unit epilogue: block-reduce, atomicAdd into per-chunk sums ----
        if ((st & 3) == 3) {
            float a = warp_red(A),  bb = warp_red(Bm), c = warp_red(C),
                  d = warp_red(D),  e = warp_red(E),  f = warp_red(F),
                  dn = warp_red(den);
            int wid = t >> 5, lane = t & 31;
            if (lane == 0) {
                red[wid][0] = a; red[wid][1] = bb; red[wid][2] = c;
                red[wid][3] = d; red[wid][4] = e;  red[wid][5] = f;
                red[wid][6] = dn;
            }
            __syncthreads();
            if (t == 0) {
                float v[7] = {0.f, 0.f, 0.f, 0.f, 0.f, 0.f, 0.f};
                #pragma unroll
                for (int w = 0; w < 8; ++w)
                    #pragma unroll
                    for (int i = 0; i < 7; ++i) v[i] += red[w][i];
                float* o = scratch + (size_t)(u >> 1) * 8;
                #pragma unroll
                for (int i = 0; i < 7; ++i) atomicAdd(o + i, v[i]);
            }
            __syncthreads();              // red[] reusable next unit
            A = Bm = C = D = E = F = den = 0.f;
        }
    }

    // ---- last CTA to finish assembles the (B, 21, 2) output ----
    if (t == 0) {
        __threadfence();
        unsigned int old = atomicAdd(&g_count, 1u);
        s_last = (old == (unsigned)grid - 1u) ? 1 : 0;
    }
    __syncthreads();

    if (s_last) {
        // phase 1: raw sums -> vf0, vf1, vs0, vs1, den (in place, slots 0..4)
        for (int c = t; c < total_chunks; c += THREADS) {
            float* s = scratch + (size_t)c * 8;
            float a  = __ldcg(s + 0), bm = __ldcg(s + 1), cc = __ldcg(s + 2),
                  d  = __ldcg(s + 3), e  = __ldcg(s + 4), f  = __ldcg(s + 5),
                  dn = __ldcg(s + 6);
            float inv = 1.f / ((dn == 0.f) ? 1.f : dn);
            s[0] = (a + e) * inv;    // vf0
            s[1] = (f - bm) * inv;   // vf1
            s[2] = (e - cc) * inv;   // vs0
            s[3] = (d + f) * inv;    // vs1
            s[4] = dn;
        }
        __syncthreads();

        // phase 2: keypoint assembly
        const int B = total_chunks / N_PHAL;
        const int total = B * 42;
        for (int o = t; o < total; o += THREADS) {
            int c = o & 1;
            int r = (o >> 1) % 21;
            int b = o / 42;
            const float* sp = scratch + (size_t)b * N_PHAL * 8;

            float val;
            if (r == 0) {
                float acc = 0.f;
                #pragma unroll
                for (int k = 0; k < 5; ++k) {
                    int p = 4 * k;
                    float dn = sp[p * 8 + 4];
                    float vf = sp[p * 8 + c];
                    acc += (dn != 0.f) ? vf : 0.f;
                }
                val = acc * 0.2f;
            } else {
                int q  = r;                  // 1..20
                int iq = (q - 1) >> 2;
                int pq = 8 * iq + 4 - q;     // 4*iq + j_q
                int jq = pq - 4 * iq;
                int pn = min(pq + 1, N_PHAL - 1);
                float vs = sp[pq * 8 + 2 + c];
                if (jq == 3) val = vs;
                else         val = 0.5f * (vs + sp[pn * 8 + c]);
            }
            out[o] = val;
        }
        __syncthreads();

        // phase 3: reset scratch + counters for the next graph replay
        for (int i = t; i < total_chunks * 8; i += THREADS) scratch[i] = 0.f;
        if (t == 0) { g_count = 0; g_next = 0; }
    }
}

extern "C" void kernel_launch(void* const* d_in, const int* in_sizes, int n_in,
                              void* d_out, int out_size)
{
    const float* x = (const float*)d_in[0];
    float* out = (float*)d_out;
    int B = in_sizes[0] / (N_PHAL * RES * RES * 5);   // 256
    int total_chunks = B * N_PHAL;                    // 5120

    float* scratch;
    cudaGetSymbolAddress((void**)&scratch, g_scratch);

    int grid = (total_chunks * 2 < GRID) ? total_chunks * 2 : GRID;
    fused_kernel<<<grid, THREADS>>>(x, scratch, out, total_chunks);
}

// round 11
// speedup vs baseline: 1.0928x; 1.0928x over previous
#include <cuda_runtime.h>
#include <cstdint>

#define RES      64
#define N_PHAL   20
#define MAX_B    256

constexpr int POS_PER_CHUNK = RES * RES;             // 4096 positions per (b,p)
constexpr int F4_PER_CHUNK  = POS_PER_CHUNK * 5 / 4; // 5120 float4s per chunk
constexpr int TILE_POS      = 2048;                  // positions per smem tile
constexpr int TILE_F4       = TILE_POS * 5 / 4;      // 2560 float4s = 40 KB
constexpr int THREADS       = 256;

// Scratch: per (b,p): vf0, vf1, vs0, vs1, den
__device__ float        g_scratch[MAX_B * N_PHAL * 5];
__device__ unsigned int g_count = 0;

__device__ __forceinline__ float warp_red(float v) {
    #pragma unroll
    for (int o = 16; o > 0; o >>= 1)
        v += __shfl_down_sync(0xffffffffu, v, o);
    return v;
}

// One block per (b, phal) chunk: stream 80 KB through SMEM, reduce 7 sums.
// (Identical schedule to the fastest measured engine; finalize fused at the end.)
__global__ __launch_bounds__(THREADS) void fused_kernel(
    const float4* __restrict__ x, float* __restrict__ scratch,
    float* __restrict__ out, int total_chunks)
{
    __shared__ float4 tile[TILE_F4];     // 40 KB
    __shared__ float  red[8][7];
    __shared__ int    s_last;

    const int chunk = blockIdx.x;        // b * N_PHAL + p
    const float4* base = x + (size_t)chunk * F4_PER_CHUNK;
    const int t = threadIdx.x;

    float A = 0.f, Bm = 0.f, C = 0.f, D = 0.f, E = 0.f, F = 0.f, den = 0.f;

    #pragma unroll
    for (int it = 0; it < 2; ++it) {
        // ---- coalesced load: 2560 float4s, 10 per thread (LDG.128 full-line) ----
        #pragma unroll
        for (int k = 0; k < 10; ++k) {
            int idx = k * THREADS + t;
            tile[idx] = base[it * TILE_F4 + idx];
        }
        __syncthreads();

        // ---- deinterleave + accumulate: each thread does 2 groups of 4 positions ----
        #pragma unroll
        for (int gs = 0; gs < 2; ++gs) {
            int g = gs * THREADS + t;            // group-of-4 index within tile
            // 5 x LDS.128 at 80B lane stride: conflict-free
            float4 v0 = tile[g * 5 + 0];
            float4 v1 = tile[g * 5 + 1];
            float4 v2 = tile[g * 5 + 2];
            float4 v3 = tile[g * 5 + 3];
            float4 v4 = tile[g * 5 + 4];

            int pos0 = it * TILE_POS + g * 4;    // first global position of group
            float fi  = (float)(pos0 >> 6);      // row (same for all 4: 4 | 64)
            float fj0 = (float)(pos0 & 63);      // first column

            // p0: f0=v0.x f1=v0.y m=v0.z d0=v0.w d1=v1.x
            { float m = v0.z, am = fabsf(m), s = m * am;
              float t0 = s * v0.x, t1 = s * v0.y;
              A  = fmaf(t1, v0.w, A);  Bm = fmaf(t0, v0.w, Bm);
              C  = fmaf(t1, v1.x, C);  D  = fmaf(t0, v1.x, D);
              E  = fmaf(am, fi, E);    F  = fmaf(am, fj0, F);
              den += am; }
            // p1: f0=v1.y f1=v1.z m=v1.w d0=v2.x d1=v2.y
            { float m = v1.w, am = fabsf(m), s = m * am;
              float t0 = s * v1.y, t1 = s * v1.z;
              A  = fmaf(t1, v2.x, A);  Bm = fmaf(t0, v2.x, Bm);
              C  = fmaf(t1, v2.y, C);  D  = fmaf(t0, v2.y, D);
              E  = fmaf(am, fi, E);    F  = fmaf(am, fj0 + 1.f, F);
              den += am; }
            // p2: f0=v2.z f1=v2.w m=v3.x d0=v3.y d1=v3.z
            { float m = v3.x, am = fabsf(m), s = m * am;
              float t0 = s * v2.z, t1 = s * v2.w;
              A  = fmaf(t1, v3.y, A);  Bm = fmaf(t0, v3.y, Bm);
              C  = fmaf(t1, v3.z, C);  D  = fmaf(t0, v3.z, D);
              E  = fmaf(am, fi, E);    F  = fmaf(am, fj0 + 2.f, F);
              den += am; }
            // p3: f0=v3.w f1=v4.x m=v4.y d0=v4.z d1=v4.w
            { float m = v4.y, am = fabsf(m), s = m * am;
              float t0 = s * v3.w, t1 = s * v4.x;
              A  = fmaf(t1, v4.z, A);  Bm = fmaf(t0, v4.z, Bm);
              C  = fmaf(t1, v4.w, C);  D  = fmaf(t0, v4.w, D);
              E  = fmaf(am, fi, E);    F  = fmaf(am, fj0 + 3.f, F);
              den += am; }
        }
        __syncthreads();   // tile reused next iteration
    }

    // ---- block reduction of 7 accumulators ----
    A = warp_red(A);  Bm = warp_red(Bm); C = warp_red(C); D = warp_red(D);
    E = warp_red(E);  F  = warp_red(F);  den = warp_red(den);

    int wid = t >> 5, lane = t & 31;
    if (lane == 0) {
        red[wid][0] = A;  red[wid][1] = Bm; red[wid][2] = C;
        red[wid][3] = D;  red[wid][4] = E;  red[wid][5] = F;
        red[wid][6] = den;
    }
    __syncthreads();

    if (t == 0) {
        float a = 0.f, b = 0.f, c = 0.f, d = 0.f, e = 0.f, f = 0.f, dn = 0.f;
        #pragma unroll
        for (int w = 0; w < 8; ++w) {
            a += red[w][0]; b += red[w][1]; c += red[w][2];
            d += red[w][3]; e += red[w][4]; f += red[w][5];
            dn += red[w][6];
        }
        float inv = 1.f / ((dn == 0.f) ? 1.f : dn);
        float* o = scratch + (size_t)chunk * 5;
        o[0] = (a + e) * inv;   // vf0
        o[1] = (f - b) * inv;   // vf1
        o[2] = (e - c) * inv;   // vs0
        o[3] = (d + f) * inv;   // vs1
        o[4] = dn;

        __threadfence();        // scratch visible before counter bump
        unsigned int old = atomicAdd(&g_count, 1u);
        s_last = (old == gridDim.x - 1u) ? 1 : 0;
    }
    __syncthreads();

    // ---- last block assembles the (B, 21, 2) output (replaces 2nd launch) ----
    if (s_last) {
        if (t == 0) g_count = 0;          // reset for next graph replay
        __threadfence();
        const int B = total_chunks / N_PHAL;
        const int total = B * 42;
        for (int o = t; o < total; o += THREADS) {
            int c = o & 1;
            int r = (o >> 1) % 21;
            int b = o / 42;
            const float* sp = scratch + (size_t)b * N_PHAL * 5;

            float val;
            if (r == 0) {
                float acc = 0.f;
                #pragma unroll
                for (int k = 0; k < 5; ++k) {
                    int p = 4 * k;
                    float dn = __ldcg(sp + p * 5 + 4);
                    float vf = __ldcg(sp + p * 5 + c);
                    acc += (dn != 0.f) ? vf : 0.f;
                }
                val = acc * 0.2f;
            } else {
                int q  = r;                  // 1..20
                int iq = (q - 1) >> 2;
                int pq = 8 * iq + 4 - q;     // 4*iq + j_q
                int jq = pq - 4 * iq;
                int pn = min(pq + 1, N_PHAL - 1);
                float vs = __ldcg(sp + pq * 5 + 2 + c);
                if (jq == 3) val = vs;
                else         val = 0.5f * (vs + __ldcg(sp + pn * 5 + c));
            }
            out[o] = val;
        }
    }
}

extern "C" void kernel_launch(void* const* d_in, const int* in_sizes, int n_in,
                              void* d_out, int out_size)
{
    const float4* x = (const float4*)d_in[0];
    float* out = (float*)d_out;
    int B = in_sizes[0] / (N_PHAL * RES * RES * 5);   // 256
    int total_chunks = B * N_PHAL;                    // 5120

    float* scratch;
    cudaGetSymbolAddress((void**)&scratch, g_scratch);

    fused_kernel<<<total_chunks, THREADS>>>(x, scratch, out, total_chunks);
}